// round 1
// baseline (speedup 1.0000x reference)
#include <cuda_runtime.h>
#include <math.h>

// ---------------- problem constants ----------------
#define Vv    32000
#define Dd    768
#define NLl   2
#define Bb    2
#define Tt    1024
#define EDe   1536
#define NSn   16
#define KC    4
#define DTR   48
#define BT    (Bb*Tt)        // 2048
#define XZc   (2*EDe)        // 3072
#define DBCP  128            // padded dbc width (80 -> 128)

// ---------------- scratch (static device globals; no allocations) ----------------
__device__ __align__(16) float g_x    [BT*Dd];     // activations (layer in/out)
__device__ __align__(16) float g_xz   [BT*XZc];    // in_proj output (xin | z)
__device__ __align__(16) float g_xin  [BT*EDe];    // conv+silu output
__device__ __align__(16) float g_dbc  [BT*DBCP];   // x_proj output, padded to 128
__device__ __align__(16) float g_delta[BT*EDe];    // dt (raw then softplus)
__device__ __align__(16) float g_du   [BT*EDe];    // delta * xin
__device__ __align__(16) float g_y    [BT*EDe];    // gated scan output
__device__ __align__(16) float g_out  [BT*Dd];     // out_proj output (pre-LN)
__device__ __align__(16) float g_xpw  [DBCP*EDe];  // padded x_proj_w

// ---------------- embedding gather (float4) ----------------
__global__ void k_embed(const int* __restrict__ tok, const float* __restrict__ emb,
                        float* __restrict__ x)
{
    int i = blockIdx.x * blockDim.x + threadIdx.x;          // over BT * (Dd/4)
    if (i >= BT * (Dd/4)) return;
    int r  = i / (Dd/4);
    int c4 = i - r * (Dd/4);
    ((float4*)x)[i] = ((const float4*)(emb + (size_t)tok[r] * Dd))[c4];
}

// ---------------- generic NT GEMM: C[M,N] = A[M,K] * B[N,K]^T (+bias) ----------------
// BM=BN=128, BK=16, 256 threads, 8x8 per thread. Requires M,N %128==0, K %16==0,
// lda/ldb/ldc such that all float4 accesses are 16B aligned (true for all call sites).
__global__ void __launch_bounds__(256) k_gemm_nt(
    const float* __restrict__ A, int lda,
    const float* __restrict__ B, int ldb,
    const float* __restrict__ bias,
    float* __restrict__ C, int ldc, int Kd)
{
    __shared__ float As[16][128];
    __shared__ float Bs[16][128];

    const int tid = threadIdx.x;
    const int bm = blockIdx.y * 128, bn = blockIdx.x * 128;

    const int r0 = tid >> 2;            // 0..63
    const int kq = (tid & 3) << 2;      // 0,4,8,12

    const float* Ap0 = A + (size_t)(bm + r0)      * lda + kq;
    const float* Ap1 = A + (size_t)(bm + r0 + 64) * lda + kq;
    const float* Bp0 = B + (size_t)(bn + r0)      * ldb + kq;
    const float* Bp1 = B + (size_t)(bn + r0 + 64) * ldb + kq;

    const int tx = tid & 15, ty = tid >> 4;

    float acc[8][8];
#pragma unroll
    for (int i = 0; i < 8; i++)
#pragma unroll
        for (int j = 0; j < 8; j++) acc[i][j] = 0.f;

    float4 ra0 = *(const float4*)Ap0;
    float4 ra1 = *(const float4*)Ap1;
    float4 rb0 = *(const float4*)Bp0;
    float4 rb1 = *(const float4*)Bp1;

    const int ntiles = Kd >> 4;
    for (int kt = 0; kt < ntiles; kt++) {
        // store (transposed) current tile
        As[kq+0][r0]    = ra0.x; As[kq+1][r0]    = ra0.y; As[kq+2][r0]    = ra0.z; As[kq+3][r0]    = ra0.w;
        As[kq+0][r0+64] = ra1.x; As[kq+1][r0+64] = ra1.y; As[kq+2][r0+64] = ra1.z; As[kq+3][r0+64] = ra1.w;
        Bs[kq+0][r0]    = rb0.x; Bs[kq+1][r0]    = rb0.y; Bs[kq+2][r0]    = rb0.z; Bs[kq+3][r0]    = rb0.w;
        Bs[kq+0][r0+64] = rb1.x; Bs[kq+1][r0+64] = rb1.y; Bs[kq+2][r0+64] = rb1.z; Bs[kq+3][r0+64] = rb1.w;
        __syncthreads();

        if (kt + 1 < ntiles) {          // prefetch next tile into registers
            Ap0 += 16; Ap1 += 16; Bp0 += 16; Bp1 += 16;
            ra0 = *(const float4*)Ap0;
            ra1 = *(const float4*)Ap1;
            rb0 = *(const float4*)Bp0;
            rb1 = *(const float4*)Bp1;
        }

#pragma unroll
        for (int kk = 0; kk < 16; kk++) {
            float a[8], bb[8];
            *(float4*)(a)      = *(const float4*)&As[kk][ty*8];
            *(float4*)(a + 4)  = *(const float4*)&As[kk][ty*8 + 4];
            *(float4*)(bb)     = *(const float4*)&Bs[kk][tx*8];
            *(float4*)(bb + 4) = *(const float4*)&Bs[kk][tx*8 + 4];
#pragma unroll
            for (int i = 0; i < 8; i++)
#pragma unroll
                for (int j = 0; j < 8; j++)
                    acc[i][j] = fmaf(a[i], bb[j], acc[i][j]);
        }
        __syncthreads();
    }

    float bv[8];
#pragma unroll
    for (int j = 0; j < 8; j++) bv[j] = bias ? bias[bn + tx*8 + j] : 0.f;

#pragma unroll
    for (int i = 0; i < 8; i++) {
        size_t row = (size_t)(bm + ty*8 + i);
        float4 o0, o1;
        o0.x = acc[i][0] + bv[0]; o0.y = acc[i][1] + bv[1];
        o0.z = acc[i][2] + bv[2]; o0.w = acc[i][3] + bv[3];
        o1.x = acc[i][4] + bv[4]; o1.y = acc[i][5] + bv[5];
        o1.z = acc[i][6] + bv[6]; o1.w = acc[i][7] + bv[7];
        *(float4*)&C[row*ldc + bn + tx*8]     = o0;
        *(float4*)&C[row*ldc + bn + tx*8 + 4] = o1;
    }
}

// ---------------- causal depthwise conv (K=4) + bias + SiLU ----------------
__global__ void k_conv(const float* __restrict__ xz, const float* __restrict__ cw,
                       const float* __restrict__ cb, float* __restrict__ xin)
{
    int i = blockIdx.x * blockDim.x + threadIdx.x;
    if (i >= BT * EDe) return;
    int bt = i / EDe, e = i - bt * EDe;
    int b = bt >> 10, t = bt & (Tt - 1);
    float s = cb[e];
    const float* col = xz + (size_t)(b * Tt) * XZc + e;
#pragma unroll
    for (int j = 0; j < KC; j++) {
        int tt = t - (KC - 1) + j;
        if (tt >= 0) s = fmaf(cw[e*KC + j], col[(size_t)tt * XZc], s);
    }
    xin[i] = s / (1.f + __expf(-s));
}

// ---------------- pad x_proj_w (80 rows) into 128-row buffer ----------------
__global__ void k_pad(const float* __restrict__ xpw, float* __restrict__ dst)
{
    int i = blockIdx.x * blockDim.x + threadIdx.x;
    if (i >= DBCP * EDe) return;
    dst[i] = (i < (DTR + 2*NSn) * EDe) ? xpw[i] : 0.f;
}

// ---------------- delta = softplus(raw + dt_b); du = delta * xin ----------------
__global__ void k_ewdelta(const float* __restrict__ dtb)
{
    int i = blockIdx.x * blockDim.x + threadIdx.x;
    if (i >= BT * EDe) return;
    int e = i % EDe;
    float raw = g_delta[i] + dtb[e];
    float sp = (raw > 20.f) ? raw : log1pf(__expf(raw));
    g_delta[i] = sp;
    g_du[i]    = sp * g_xin[i];
}

// ---------------- selective scan: warp = 2 channels x 16 states ----------------
__global__ void k_scan(const float* __restrict__ a_log, const float* __restrict__ d_par)
{
    int gid  = blockIdx.x * blockDim.x + threadIdx.x;
    int warp = gid >> 5, lane = gid & 31;
    if (warp >= Bb * (EDe/2)) return;
    int b  = warp / (EDe/2);
    int ep = warp - b * (EDe/2);
    int e  = ep * 2 + (lane >> 4);
    int n  = lane & 15;

    float Ac = -__expf(a_log[e*NSn + n]);
    float dp = d_par[e];
    float h  = 0.f;
    size_t baseBT = (size_t)b * Tt;

    for (int t = 0; t < Tt; t++) {
        size_t bt = baseBT + t;
        float dv  = g_delta[bt*EDe + e];
        float duv = g_du   [bt*EDe + e];
        float Bv  = g_dbc  [bt*DBCP + DTR + n];
        float Cv  = g_dbc  [bt*DBCP + DTR + NSn + n];
        float dA  = __expf(dv * Ac);
        h = fmaf(dA, h, duv * Bv);
        float c = h * Cv;
        c += __shfl_xor_sync(0xffffffffu, c, 8);
        c += __shfl_xor_sync(0xffffffffu, c, 4);
        c += __shfl_xor_sync(0xffffffffu, c, 2);
        c += __shfl_xor_sync(0xffffffffu, c, 1);
        if (n == 0) {
            float xv = g_xin[bt*EDe + e];
            float zv = g_xz [bt*XZc + EDe + e];
            float gt = zv / (1.f + __expf(-zv));
            g_y[bt*EDe + e] = (c + dp * xv) * gt;
        }
    }
}

// ---------------- LayerNorm over D=768, writes into g_x ----------------
__global__ void k_ln(const float* __restrict__ w, const float* __restrict__ b)
{
    int row = blockIdx.x, tid = threadIdx.x;     // 256 threads
    const float* r = g_out + (size_t)row * Dd;
    float v0 = r[tid], v1 = r[tid+256], v2 = r[tid+512];
    float s  = v0 + v1 + v2;
    float sq = v0*v0 + v1*v1 + v2*v2;
#pragma unroll
    for (int o = 16; o; o >>= 1) {
        s  += __shfl_xor_sync(0xffffffffu, s,  o);
        sq += __shfl_xor_sync(0xffffffffu, sq, o);
    }
    __shared__ float ss[8], sqq[8];
    if ((tid & 31) == 0) { ss[tid>>5] = s; sqq[tid>>5] = sq; }
    __syncthreads();
    s = 0.f; sq = 0.f;
#pragma unroll
    for (int i = 0; i < 8; i++) { s += ss[i]; sq += sqq[i]; }
    float mu  = s * (1.f / Dd);
    float var = sq * (1.f / Dd) - mu * mu;
    float inv = rsqrtf(var + 1e-5f);
    float* o = g_x + (size_t)row * Dd;
    o[tid]     = (v0 - mu) * inv * w[tid]     + b[tid];
    o[tid+256] = (v1 - mu) * inv * w[tid+256] + b[tid+256];
    o[tid+512] = (v2 - mu) * inv * w[tid+512] + b[tid+512];
}

// ---------------- launch ----------------
extern "C" void kernel_launch(void* const* d_in, const int* in_sizes, int n_in,
                              void* d_out, int out_size)
{
    const int*   tokens = (const int*)  d_in[0];
    const float* embed  = (const float*)d_in[1];
    const float* in_w   = (const float*)d_in[2];
    const float* conv_w = (const float*)d_in[3];
    const float* conv_b = (const float*)d_in[4];
    const float* xp_w   = (const float*)d_in[5];
    const float* dt_w   = (const float*)d_in[6];
    const float* dt_b   = (const float*)d_in[7];
    const float* a_log  = (const float*)d_in[8];
    const float* d_par  = (const float*)d_in[9];
    const float* out_w  = (const float*)d_in[10];
    const float* ln_w   = (const float*)d_in[11];
    const float* ln_b   = (const float*)d_in[12];
    const float* head_w = (const float*)d_in[13];
    const float* head_b = (const float*)d_in[14];
    float* out = (float*)d_out;

    float *p_x, *p_xz, *p_xin, *p_dbc, *p_delta, *p_y, *p_out, *p_xpw;
    cudaGetSymbolAddress((void**)&p_x,     g_x);
    cudaGetSymbolAddress((void**)&p_xz,    g_xz);
    cudaGetSymbolAddress((void**)&p_xin,   g_xin);
    cudaGetSymbolAddress((void**)&p_dbc,   g_dbc);
    cudaGetSymbolAddress((void**)&p_delta, g_delta);
    cudaGetSymbolAddress((void**)&p_y,     g_y);
    cudaGetSymbolAddress((void**)&p_out,   g_out);
    cudaGetSymbolAddress((void**)&p_xpw,   g_xpw);

    // embed
    k_embed<<<(BT*(Dd/4) + 255)/256, 256>>>(tokens, embed, p_x);

    for (int l = 0; l < NLl; l++) {
        // in_proj: xz = x @ in_w^T   (M=2048, N=3072, K=768)
        k_gemm_nt<<<dim3(XZc/128, BT/128), 256>>>(
            p_x, Dd, in_w + (size_t)l*XZc*Dd, Dd, nullptr, p_xz, XZc, Dd);

        // conv + silu
        k_conv<<<(BT*EDe + 255)/256, 256>>>(p_xz, conv_w + (size_t)l*EDe*KC,
                                            conv_b + (size_t)l*EDe, p_xin);

        // pad x_proj_w and x_proj GEMM (M=2048, N=128, K=1536)
        k_pad<<<(DBCP*EDe + 255)/256, 256>>>(xp_w + (size_t)l*(DTR+2*NSn)*EDe, p_xpw);
        k_gemm_nt<<<dim3(1, BT/128), 256>>>(
            p_xin, EDe, p_xpw, EDe, nullptr, p_dbc, DBCP, EDe);

        // dt_proj GEMM (M=2048, N=1536, K=48) -> raw delta
        k_gemm_nt<<<dim3(EDe/128, BT/128), 256>>>(
            p_dbc, DBCP, dt_w + (size_t)l*EDe*DTR, DTR, nullptr, p_delta, EDe, DTR);

        // softplus + du
        k_ewdelta<<<(BT*EDe + 255)/256, 256>>>(dt_b + (size_t)l*EDe);

        // selective scan + D skip + gate
        k_scan<<<(Bb*(EDe/2)*32 + 255)/256, 256>>>(a_log + (size_t)l*EDe*NSn,
                                                   d_par + (size_t)l*EDe);

        // out_proj GEMM (M=2048, N=768, K=1536)
        k_gemm_nt<<<dim3(Dd/128, BT/128), 256>>>(
            p_y, EDe, out_w + (size_t)l*Dd*EDe, EDe, nullptr, p_out, Dd, EDe);

        // layernorm -> g_x
        k_ln<<<BT, 256>>>(ln_w + (size_t)l*Dd, ln_b + (size_t)l*Dd);
    }

    // head GEMM (M=2048, N=32000, K=768) + bias -> output
    k_gemm_nt<<<dim3(Vv/128, BT/128), 256>>>(
        p_x, Dd, head_w, Dd, head_b, out, Vv, Dd);

    (void)in_sizes; (void)n_in; (void)out_size;
}